// round 15
// baseline (speedup 1.0000x reference)
#include <cuda_runtime.h>
#include <cuda_bf16.h>
#include <cuda_fp16.h>
#include <cstdint>

#define BB 8
#define NN 2048
#define CC 256
#define FF 128
#define MTOT (BB*NN)   // 16384

// ---------------- scratch (no cudaMalloc allowed) ----------------
__device__ __half        g_fx16[MTOT*FF];          // 4 MB
__device__ __half        g_gx16[MTOT*FF];          // 4 MB
__device__ float         g_hx [MTOT*FF];           // 8 MB
__device__ __half        g_hxT[(size_t)BB*FF*NN];  // [b][f][n] fp16 (scaled)
__device__ __half        g_eT[(size_t)BB*NN*NN];   // [b][m][n] fp16, 64 MB
__device__ float         g_rowsum[BB*NN];          // full row sums
__device__ float         g_O [MTOT*FF];            // [b][f][m] 8 MB
__device__ __half        g_Wt[3*FF*CC];            // Wf/Wg/Wh transposed fp16 [o][col][k]
__device__ __half        g_Wvt[FF*FF];             // Wv transposed fp16 [col][k]

#define HXT_SCALE 16384.0f
#define HXT_INV_SCALE (1.0f/16384.0f)

// ======================= PTX helpers =======================
__device__ __forceinline__ uint32_t smem_to_u32(const void* p) {
    uint32_t a;
    asm("{ .reg .u64 t; cvta.to.shared.u64 t, %1; cvt.u32.u64 %0, t; }" : "=r"(a) : "l"(p));
    return a;
}
#define CP_ASYNC16(dst, src) \
    asm volatile("cp.async.cg.shared.global [%0], [%1], 16;" :: "r"(dst), "l"(src) : "memory")
#define CP_COMMIT() asm volatile("cp.async.commit_group;" ::: "memory")
#define CP_WAIT(n)  asm volatile("cp.async.wait_group %0;" :: "n"(n) : "memory")

__device__ __forceinline__ void ldsm_x4(uint32_t& r0, uint32_t& r1, uint32_t& r2, uint32_t& r3, uint32_t a) {
    asm volatile("ldmatrix.sync.aligned.m8n8.x4.shared.b16 {%0,%1,%2,%3}, [%4];"
                 : "=r"(r0), "=r"(r1), "=r"(r2), "=r"(r3) : "r"(a));
}
__device__ __forceinline__ void ldsm_x2(uint32_t& r0, uint32_t& r1, uint32_t a) {
    asm volatile("ldmatrix.sync.aligned.m8n8.x2.shared.b16 {%0,%1}, [%2];"
                 : "=r"(r0), "=r"(r1) : "r"(a));
}
__device__ __forceinline__ void mma_f16(float c[4], const uint32_t a[4], const uint32_t b[2]) {
    asm volatile("mma.sync.aligned.m16n8k16.row.col.f32.f16.f16.f32 "
                 "{%0,%1,%2,%3}, {%4,%5,%6,%7}, {%8,%9}, {%0,%1,%2,%3};"
                 : "+f"(c[0]), "+f"(c[1]), "+f"(c[2]), "+f"(c[3])
                 : "r"(a[0]), "r"(a[1]), "r"(a[2]), "r"(a[3]), "r"(b[0]), "r"(b[1]));
}

// =================================================================
// wprep: transpose weights to fp16 [col][k] for MMA B operands
// =================================================================
__global__ __launch_bounds__(256) void wprep(
    const float* __restrict__ Wf, const float* __restrict__ Wg,
    const float* __restrict__ Wh, const float* __restrict__ Wv)
{
    const int stride = gridDim.x * 256;
    for (int i = blockIdx.x * 256 + threadIdx.x; i < 3*FF*CC; i += stride) {
        int o = i / (FF*CC);
        int rem = i - o * (FF*CC);
        int c = rem >> 8;
        int k = rem & 255;
        const float* W = (o == 0) ? Wf : (o == 1) ? Wg : Wh;
        g_Wt[i] = __float2half(W[k * FF + c]);
    }
    for (int i = blockIdx.x * 256 + threadIdx.x; i < FF*FF; i += stride) {
        int c = i >> 7, k = i & 127;
        g_Wvt[i] = __float2half(Wv[k * FF + c]);
    }
}

// =================================================================
// proj_mma: fused 3-way projection via fp16 HMMA. (measured-good R13)
// =================================================================
#define PJ_XS    0
#define PJ_XCH   9216
#define PJ_W     36864
#define PJ_WBUF  55296
#define PJ_WO    18432
#define PJ_SMEM  147456

__global__ __launch_bounds__(256, 1) void proj_mma(
    const float* __restrict__ x,
    const float* __restrict__ bf, const float* __restrict__ bg,
    const float* __restrict__ bh)
{
    extern __shared__ char smem[];
    const uint32_t sb = smem_to_u32(smem);
    const int tid  = threadIdx.x;
    const int lane = tid & 31, wid = tid >> 5;
    const int R0 = (wid >> 2) * 32;
    const int C0 = (wid & 3) * 32;
    const int row0 = blockIdx.x * 64;

    #pragma unroll
    for (int c = 0; c < 2; c++) {
        uint32_t bufb = sb + PJ_W + (uint32_t)c * PJ_WBUF;
        #pragma unroll
        for (int o = 0; o < 3; o++) {
            const __half* src0 = g_Wt + o * (FF*CC);
            #pragma unroll
            for (int e = tid; e < 1024; e += 256) {
                int col = e >> 3, seg = e & 7;
                CP_ASYNC16(bufb + (uint32_t)(o*PJ_WO + col*144 + seg*16),
                           src0 + col*CC + c*64 + seg*8);
            }
        }
        CP_COMMIT();
    }

    for (int e = tid; e < 4096; e += 256) {
        int r = e >> 6, seg = e & 63;
        int k = seg * 4;
        float4 v = *(const float4*)&x[(size_t)(row0 + r) * CC + k];
        __half h4[4] = { __float2half(v.x), __float2half(v.y),
                         __float2half(v.z), __float2half(v.w) };
        uint32_t off = PJ_XS + (uint32_t)(k >> 6) * PJ_XCH + r*144 + (k & 63)*2;
        *(uint2*)(smem + off) = *(const uint2*)h4;
    }
    __syncthreads();

    float acc[3][2][4][4];
    #pragma unroll
    for (int o = 0; o < 3; o++)
        #pragma unroll
        for (int mi = 0; mi < 2; mi++)
            #pragma unroll
            for (int ni = 0; ni < 4; ni++)
                #pragma unroll
                for (int q = 0; q < 4; q++) acc[o][mi][ni][q] = 0.f;

    const int arow  = R0 + (lane & 15);
    const int acolB = ((lane >> 4) << 3);
    const int l15   = lane & 15;
    const int brow  = C0 + (l15 & 7);
    const int bcolB = ((l15 >> 3) << 3);

    for (int c = 0; c < 4; c++) {
        if (c < 3) { CP_WAIT(1); } else { CP_WAIT(0); }
        __syncthreads();
        const uint32_t xb = sb + PJ_XS + (uint32_t)c * PJ_XCH;
        const uint32_t wb = sb + PJ_W + (uint32_t)(c & 1) * PJ_WBUF;
        #pragma unroll
        for (int ks = 0; ks < 4; ks++) {
            const int k0 = ks * 16;
            uint32_t aH[2][4];
            #pragma unroll
            for (int mi = 0; mi < 2; mi++) {
                uint32_t ad = xb + (uint32_t)(((arow + mi*16)*72 + k0 + acolB) * 2);
                ldsm_x4(aH[mi][0], aH[mi][1], aH[mi][2], aH[mi][3], ad);
            }
            #pragma unroll
            for (int o = 0; o < 3; o++) {
                uint32_t bH[4][2];
                #pragma unroll
                for (int ni = 0; ni < 4; ni++) {
                    uint32_t bd = wb + (uint32_t)(o*PJ_WO + ((brow + ni*8)*72 + k0 + bcolB) * 2);
                    ldsm_x2(bH[ni][0], bH[ni][1], bd);
                }
                #pragma unroll
                for (int mi = 0; mi < 2; mi++)
                    #pragma unroll
                    for (int ni = 0; ni < 4; ni++)
                        mma_f16(acc[o][mi][ni], aH[mi], bH[ni]);
            }
        }
        __syncthreads();
        if (c + 2 < 4) {
            uint32_t bufb = sb + PJ_W + (uint32_t)(c & 1) * PJ_WBUF;
            #pragma unroll
            for (int o = 0; o < 3; o++) {
                const __half* src0 = g_Wt + o * (FF*CC);
                #pragma unroll
                for (int e = tid; e < 1024; e += 256) {
                    int col = e >> 3, seg = e & 7;
                    CP_ASYNC16(bufb + (uint32_t)(o*PJ_WO + col*144 + seg*16),
                               src0 + col*CC + (c+2)*64 + seg*8);
                }
            }
            CP_COMMIT();
        }
    }

    #pragma unroll
    for (int mi = 0; mi < 2; mi++)
        #pragma unroll
        for (int ni = 0; ni < 4; ni++) {
            int r0q = row0 + R0 + mi*16 + (lane >> 2);
            int col = C0 + ni*8 + 2*(lane & 3);
            float bfc0 = bf[col], bfc1 = bf[col+1];
            float bgc0 = bg[col], bgc1 = bg[col+1];
            float bhc0 = bh[col], bhc1 = bh[col+1];
            #pragma unroll
            for (int h = 0; h < 2; h++) {
                int r = r0q + h*8;
                size_t o = (size_t)r * FF + col;
                __half2 vf = { __float2half(acc[0][mi][ni][h*2+0] + bfc0),
                               __float2half(acc[0][mi][ni][h*2+1] + bfc1) };
                __half2 vg = { __float2half(acc[1][mi][ni][h*2+0] + bgc0),
                               __float2half(acc[1][mi][ni][h*2+1] + bgc1) };
                float2 vh = { acc[2][mi][ni][h*2+0] + bhc0,
                              acc[2][mi][ni][h*2+1] + bhc1 };
                *(__half2*)&g_fx16[o] = vf;
                *(__half2*)&g_gx16[o] = vg;
                *(float2*)&g_hx[o]    = vh;
            }
        }
}

// =================================================================
// score_mma: PERSISTENT-ROW version. grid (it=16, b=8) = 128 CTAs.
// A tile (fx 128x128) resident in smem; loop over 16 jt B tiles with
// double-buffered cp.async. Rowsums accumulate in regs across full row.
// epilogue per jt: exp, stage transpose, fp16 store to g_eT.
// =================================================================
#define SP_A    0          // 128*272 = 34816
#define SP_B0   34816
#define SP_B1   69632
#define SP_ST   104448     // stage 128*136*2 = 34816
#define SP_RED  139264     // float[128]
#define SP_SMEM 139776

__global__ __launch_bounds__(256, 1) void score_mma()
{
    extern __shared__ char smem[];
    const uint32_t sb = smem_to_u32(smem);
    const int tid  = threadIdx.x;
    const int lane = tid & 31, wid = tid >> 5;
    const int wrow = wid >> 2, wcol = wid & 3;
    const int R0 = wrow * 64, C0 = wcol * 32;
    const int it = blockIdx.x, b = blockIdx.y;
    const int row0 = it * 128;

    const __half* fx  = g_fx16 + (size_t)(b*NN + row0) * FF;
    const __half* gxb = g_gx16 + (size_t)(b*NN) * FF;

    // fill A (resident)
    #pragma unroll
    for (int e = tid; e < 2048; e += 256) {
        int r = e >> 4, s = e & 15;
        CP_ASYNC16(sb + SP_A + (uint32_t)(r*272 + s*16), fx + (size_t)r * FF + s*8);
    }
    CP_COMMIT();

    auto fillB = [&](int buf, int jt) {
        uint32_t bufb = sb + SP_B0 + (uint32_t)buf * 34816;
        const __half* gx = gxb + (size_t)(jt*128) * FF;
        #pragma unroll
        for (int e = tid; e < 2048; e += 256) {
            int r = e >> 4, s = e & 15;
            CP_ASYNC16(bufb + (uint32_t)(r*272 + s*16), gx + (size_t)r * FF + s*8);
        }
        CP_COMMIT();
    };
    fillB(0, 0);
    fillB(1, 1);

    float* red = (float*)(smem + SP_RED);
    if (tid < 128) red[tid] = 0.f;

    float rs[4][2];
    #pragma unroll
    for (int mi = 0; mi < 4; mi++) { rs[mi][0] = 0.f; rs[mi][1] = 0.f; }

    const int arow  = R0 + (lane & 15);
    const int acolB = ((lane >> 4) << 3);
    const int l15   = lane & 15;
    const int brow  = C0 + (l15 & 7);
    const int bcolB = ((l15 >> 3) << 3);
    __half* stage = (__half*)(smem + SP_ST);

    for (int jt = 0; jt < 16; jt++) {
        if (jt == 15) { CP_WAIT(0); } else { CP_WAIT(1); }
        __syncthreads();
        const uint32_t bbuf = sb + SP_B0 + (uint32_t)(jt & 1) * 34816;
        const int col0 = jt * 128;

        float acc[4][4][4];
        #pragma unroll
        for (int mi = 0; mi < 4; mi++)
            #pragma unroll
            for (int ni = 0; ni < 4; ni++)
                #pragma unroll
                for (int q = 0; q < 4; q++) acc[mi][ni][q] = 0.f;

        #pragma unroll
        for (int ks = 0; ks < 8; ks++) {
            const int k0 = ks * 16;
            uint32_t aH[4][4], bH[4][2];
            #pragma unroll
            for (int mi = 0; mi < 4; mi++) {
                uint32_t ad = sb + SP_A + (uint32_t)(((arow + mi*16)*136 + k0 + acolB) * 2);
                ldsm_x4(aH[mi][0], aH[mi][1], aH[mi][2], aH[mi][3], ad);
            }
            #pragma unroll
            for (int ni = 0; ni < 4; ni++) {
                uint32_t bd = bbuf + (uint32_t)(((brow + ni*8)*136 + k0 + bcolB) * 2);
                ldsm_x2(bH[ni][0], bH[ni][1], bd);
            }
            #pragma unroll
            for (int mi = 0; mi < 4; mi++)
                #pragma unroll
                for (int ni = 0; ni < 4; ni++)
                    mma_f16(acc[mi][ni], aH[mi], bH[ni]);
        }
        __syncthreads();   // all warps done reading B[jt&1] (and prior stage store done)

        // prefetch B for jt+2 (overlaps epilogue)
        if (jt + 2 < 16) fillB(jt & 1, jt + 2);

        // epilogue: exp, accumulate rowsums, stage transposed
        #pragma unroll
        for (int mi = 0; mi < 4; mi++) {
            #pragma unroll
            for (int ni = 0; ni < 4; ni++) {
                acc[mi][ni][0] = __expf(acc[mi][ni][0]);
                acc[mi][ni][1] = __expf(acc[mi][ni][1]);
                acc[mi][ni][2] = __expf(acc[mi][ni][2]);
                acc[mi][ni][3] = __expf(acc[mi][ni][3]);
                rs[mi][0] += acc[mi][ni][0] + acc[mi][ni][1];
                rs[mi][1] += acc[mi][ni][2] + acc[mi][ni][3];
                #pragma unroll
                for (int q = 0; q < 4; q++) {
                    int i = R0 + mi*16 + (lane >> 2) + ((q >> 1) << 3);
                    int j = C0 + ni*8 + 2*(lane & 3) + (q & 1);
                    stage[j*136 + i] = __float2half(acc[mi][ni][q]);
                }
            }
        }
        __syncthreads();
        {
            int j = tid >> 1, half = tid & 1;
            uint4* dst = (uint4*)(g_eT + ((size_t)(b*NN + col0 + j))*NN + row0 + half*64);
            const uint4* src = (const uint4*)(stage + j*136 + half*64);
            #pragma unroll
            for (int i = 0; i < 8; i++) dst[i] = src[i];
        }
    }

    // final rowsum reduction -> g_rowsum
    __syncthreads();
    #pragma unroll
    for (int mi = 0; mi < 4; mi++) {
        float s0 = rs[mi][0], s1 = rs[mi][1];
        s0 += __shfl_xor_sync(0xffffffffu, s0, 1);
        s0 += __shfl_xor_sync(0xffffffffu, s0, 2);
        s1 += __shfl_xor_sync(0xffffffffu, s1, 1);
        s1 += __shfl_xor_sync(0xffffffffu, s1, 2);
        if ((lane & 3) == 0) {
            int r = R0 + mi*16 + (lane >> 2);
            atomicAdd(&red[r], s0);
            atomicAdd(&red[r + 8], s1);
        }
    }
    __syncthreads();
    if (tid < 128)
        g_rowsum[b*NN + row0 + tid] = red[tid];
}

// =================================================================
// hxT_kernel: hxT[b][f][n] = fp16( hx[b][n][f]/rowsum[n] * 2^14 )
// (R14 measured-good; now reads g_rowsum directly)
// =================================================================
__global__ __launch_bounds__(256) void hxT_kernel()
{
    __shared__ __half stage[128][72];
    __shared__ float inv[64];
    const int b = blockIdx.y, n0 = blockIdx.x * 64, t = threadIdx.x;

    if (t < 64)
        inv[t] = HXT_SCALE / g_rowsum[b*NN + n0 + t];
    __syncthreads();

    const float* hx = g_hx + ((size_t)(b*NN + n0)) * FF;

    #pragma unroll
    for (int idx = t; idx < 2048; idx += 256) {
        int r = idx >> 5;
        int seg = idx & 31;
        float4 v = *(const float4*)&hx[(size_t)r * FF + seg*4];
        float s = inv[r];
        stage[seg*4+0][r] = __float2half(v.x * s);
        stage[seg*4+1][r] = __float2half(v.y * s);
        stage[seg*4+2][r] = __float2half(v.z * s);
        stage[seg*4+3][r] = __float2half(v.w * s);
    }
    __syncthreads();

    {
        int f = t & 127, part = t >> 7;
        uint4* dst = (uint4*)(g_hxT + ((size_t)(b*FF) + f) * NN + n0 + part*32);
        const uint4* src = (const uint4*)&stage[f][part*32];
        #pragma unroll
        for (int i = 0; i < 4; i++) dst[i] = src[i];
    }
}

// =================================================================
// out_mma: (R14 measured-good 4x2 layout version, untouched)
// =================================================================
#define O_A  0
#define O_B  18432
#define O_CH 27648
#define OT_SMEM (3*O_CH)

__global__ __launch_bounds__(256, 2) void out_mma()
{
    extern __shared__ char smem[];
    const uint32_t sb = smem_to_u32(smem);
    const int tid  = threadIdx.x;
    const int lane = tid & 31, wid = tid >> 5;
    const int wrow = wid & 3;
    const int wcol = wid >> 2;
    const int R0 = wrow * 32;
    const int C0 = wcol * 32;
    const int b = blockIdx.y, m0 = blockIdx.x * 64;

    const __half* Ah = g_hxT + (size_t)b * FF * NN;
    const __half* Bm = g_eT + (size_t)b * NN * NN + (size_t)m0 * NN;

    auto fill = [&](int buf, int kc) {
        uint32_t bufb = sb + (uint32_t)buf * O_CH;
        #pragma unroll
        for (int e = tid; e < 1024; e += 256) {
            int r = e >> 3, s = e & 7;
            size_t go = (size_t)r * NN + (size_t)kc*64 + s*8;
            CP_ASYNC16(bufb + O_A + (uint32_t)(r*144 + s*16), Ah + go);
        }
        #pragma unroll
        for (int e = tid; e < 512; e += 256) {
            int r = e >> 3, s = e & 7;
            size_t go = (size_t)r * NN + (size_t)kc*64 + s*8;
            CP_ASYNC16(bufb + O_B + (uint32_t)(r*144 + s*16), Bm + go);
        }
        CP_COMMIT();
    };

    float acc[2][4][4];
    #pragma unroll
    for (int mi = 0; mi < 2; mi++)
        #pragma unroll
        for (int ni = 0; ni < 4; ni++)
            #pragma unroll
            for (int q = 0; q < 4; q++) acc[mi][ni][q] = 0.f;

    fill(0, 0);
    fill(1, 1);
    fill(2, 2);

    const int arow  = R0 + (lane & 15);
    const int acolB = ((lane >> 4) << 3);
    const int bn0   = C0 + ((lane >> 4) << 3) + (lane & 7);
    const int bk    = ((lane >> 3) & 1) << 3;

    for (int kc = 0; kc < 32; kc++) {
        if (kc == 31)      { CP_WAIT(0); }
        else if (kc == 30) { CP_WAIT(1); }
        else               { CP_WAIT(2); }
        __syncthreads();
        uint32_t bufb = sb + (uint32_t)(kc % 3) * O_CH;
        #pragma unroll
        for (int ks = 0; ks < 4; ks++) {
            const int k0 = ks * 16;
            uint32_t aH[2][4], bb[2][4];
            #pragma unroll
            for (int mi = 0; mi < 2; mi++) {
                uint32_t ad = bufb + O_A + (uint32_t)(((arow + mi*16)*72 + k0 + acolB) * 2);
                ldsm_x4(aH[mi][0], aH[mi][1], aH[mi][2], aH[mi][3], ad);
            }
            #pragma unroll
            for (int g = 0; g < 2; g++) {
                uint32_t bd = bufb + O_B + (uint32_t)(((bn0 + g*16)*72 + k0 + bk) * 2);
                ldsm_x4(bb[g][0], bb[g][1], bb[g][2], bb[g][3], bd);
            }
            #pragma unroll
            for (int mi = 0; mi < 2; mi++)
                #pragma unroll
                for (int g = 0; g < 2; g++) {
                    mma_f16(acc[mi][g*2+0], aH[mi], &bb[g][0]);
                    mma_f16(acc[mi][g*2+1], aH[mi], &bb[g][2]);
                }
        }
        __syncthreads();
        if (kc + 3 < 32) fill(kc % 3, kc + 3);
    }

    #pragma unroll
    for (int mi = 0; mi < 2; mi++)
        #pragma unroll
        for (int ni = 0; ni < 4; ni++) {
            int f = R0 + mi*16 + (lane >> 2);
            int m = m0 + C0 + ni*8 + 2*(lane & 3);
            float2 v0 = { acc[mi][ni][0]*HXT_INV_SCALE, acc[mi][ni][1]*HXT_INV_SCALE };
            float2 v1 = { acc[mi][ni][2]*HXT_INV_SCALE, acc[mi][ni][3]*HXT_INV_SCALE };
            *(float2*)&g_O[((size_t)(b*FF) + f    ) * NN + m] = v0;
            *(float2*)&g_O[((size_t)(b*FF) + f + 8) * NN + m] = v1;
        }
}

// =================================================================
// final_mma: (R13 measured-good, untouched)
// =================================================================
#define FN_XS   0
#define FN_XCH  9216
#define FN_W    18432
#define FN_WCH  18432
#define FN_SMEM 55296

__global__ __launch_bounds__(256) void final_mma(
    const float* __restrict__ bv, float* __restrict__ out)
{
    extern __shared__ char smem[];
    const uint32_t sb = smem_to_u32(smem);
    const int tid  = threadIdx.x;
    const int lane = tid & 31, wid = tid >> 5;
    const int R0 = (wid >> 2) * 32;
    const int C0 = (wid & 3) * 32;
    const int row0 = blockIdx.x * 64;

    #pragma unroll
    for (int c = 0; c < 2; c++) {
        #pragma unroll
        for (int e = tid; e < 1024; e += 256) {
            int col = e >> 3, seg = e & 7;
            CP_ASYNC16(sb + FN_W + (uint32_t)(c*FN_WCH + col*144 + seg*16),
                       g_Wvt + col*FF + c*64 + seg*8);
        }
    }
    CP_COMMIT();

    const float* A = (const float*)g_O;
    for (int e = tid; e < 2048; e += 256) {
        int r = e >> 5, seg = e & 31;
        int k = seg * 4;
        float4 v = *(const float4*)&A[(size_t)(row0 + r) * FF + k];
        __half h4[4] = { __float2half(v.x), __float2half(v.y),
                         __float2half(v.z), __float2half(v.w) };
        uint32_t off = FN_XS + (uint32_t)(k >> 6) * FN_XCH + r*144 + (k & 63)*2;
        *(uint2*)(smem + off) = *(const uint2*)h4;
    }
    CP_WAIT(0);
    __syncthreads();

    float acc[2][4][4];
    #pragma unroll
    for (int mi = 0; mi < 2; mi++)
        #pragma unroll
        for (int ni = 0; ni < 4; ni++)
            #pragma unroll
            for (int q = 0; q < 4; q++) acc[mi][ni][q] = 0.f;

    const int arow  = R0 + (lane & 15);
    const int acolB = ((lane >> 4) << 3);
    const int l15   = lane & 15;
    const int brow  = C0 + (l15 & 7);
    const int bcolB = ((l15 >> 3) << 3);

    #pragma unroll
    for (int c = 0; c < 2; c++) {
        const uint32_t xb = sb + FN_XS + (uint32_t)c * FN_XCH;
        const uint32_t wb = sb + FN_W  + (uint32_t)c * FN_WCH;
        #pragma unroll
        for (int ks = 0; ks < 4; ks++) {
            const int k0 = ks * 16;
            uint32_t aH[2][4], bH[4][2];
            #pragma unroll
            for (int mi = 0; mi < 2; mi++) {
                uint32_t ad = xb + (uint32_t)(((arow + mi*16)*72 + k0 + acolB) * 2);
                ldsm_x4(aH[mi][0], aH[mi][1], aH[mi][2], aH[mi][3], ad);
            }
            #pragma unroll
            for (int ni = 0; ni < 4; ni++) {
                uint32_t bd = wb + (uint32_t)(((brow + ni*8)*72 + k0 + bcolB) * 2);
                ldsm_x2(bH[ni][0], bH[ni][1], bd);
            }
            #pragma unroll
            for (int mi = 0; mi < 2; mi++)
                #pragma unroll
                for (int ni = 0; ni < 4; ni++)
                    mma_f16(acc[mi][ni], aH[mi], bH[ni]);
        }
    }

    #pragma unroll
    for (int mi = 0; mi < 2; mi++)
        #pragma unroll
        for (int ni = 0; ni < 4; ni++) {
            int r0q = row0 + R0 + mi*16 + (lane >> 2);
            int col = C0 + ni*8 + 2*(lane & 3);
            float b0 = bv[col], b1 = bv[col+1];
            #pragma unroll
            for (int h = 0; h < 2; h++) {
                int r = r0q + h*8;
                float2 v = { acc[mi][ni][h*2+0] + b0, acc[mi][ni][h*2+1] + b1 };
                *(float2*)&out[(size_t)r * FF + col] = v;
            }
        }
}

// =================================================================
extern "C" void kernel_launch(void* const* d_in, const int* in_sizes, int n_in,
                              void* d_out, int out_size)
{
    const float* x  = (const float*)d_in[0];
    const float* Wf = (const float*)d_in[1];
    const float* bf = (const float*)d_in[2];
    const float* Wg = (const float*)d_in[3];
    const float* bg = (const float*)d_in[4];
    const float* Wh = (const float*)d_in[5];
    const float* bh = (const float*)d_in[6];
    const float* Wv = (const float*)d_in[7];
    const float* bv = (const float*)d_in[8];
    float* out = (float*)d_out;

    cudaFuncSetAttribute(proj_mma,  cudaFuncAttributeMaxDynamicSharedMemorySize, PJ_SMEM);
    cudaFuncSetAttribute(score_mma, cudaFuncAttributeMaxDynamicSharedMemorySize, SP_SMEM);
    cudaFuncSetAttribute(out_mma,   cudaFuncAttributeMaxDynamicSharedMemorySize, OT_SMEM);
    cudaFuncSetAttribute(final_mma, cudaFuncAttributeMaxDynamicSharedMemorySize, FN_SMEM);

    // weight transpose + fp16 conversion
    wprep<<<128, 256>>>(Wf, Wg, Wh, Wv);

    // fused projections via HMMA: fx/gx -> fp16, hx -> fp32
    proj_mma<<<MTOT/64, 256, PJ_SMEM>>>(x, bf, bg, bh);

    // scores + exp + transposed fp16 store + full row sums (persistent-row)
    score_mma<<<dim3(16, 8), 256, SP_SMEM>>>();

    // hxT = hx / rowsum * 2^14, transposed, fp16
    hxT_kernel<<<dim3(32, 8), 256>>>();

    // O = hxT @ eT^T * 2^-14
    out_mma<<<dim3(32, 8), 256, OT_SMEM>>>();

    // final: reshape([B,F,N] flat as [B,N,F]) @ Wv + bv via HMMA
    final_mma<<<MTOT/64, 256, FN_SMEM>>>(bv, out);
}

// round 16
// speedup vs baseline: 1.0198x; 1.0198x over previous
#include <cuda_runtime.h>
#include <cuda_bf16.h>
#include <cuda_fp16.h>
#include <cstdint>

#define BB 8
#define NN 2048
#define CC 256
#define FF 128
#define MTOT (BB*NN)   // 16384

// ---------------- scratch (no cudaMalloc allowed) ----------------
__device__ __half        g_fx16[MTOT*FF];          // 4 MB
__device__ __half        g_gx16[MTOT*FF];          // 4 MB
__device__ float         g_hx [MTOT*FF];           // 8 MB
__device__ __half        g_hxT[(size_t)BB*FF*NN];  // [b][f][n] fp16 (scaled)
__device__ __half        g_eT[(size_t)BB*NN*NN];   // [b][m][n] fp16, 64 MB
__device__ float         g_spart[(size_t)BB*NN*16];// partial row sums
__device__ float         g_O [MTOT*FF];            // [b][f][m] 8 MB
__device__ __half        g_Wt[3*FF*CC];            // Wf/Wg/Wh transposed fp16 [o][col][k]
__device__ __half        g_Wvt[FF*FF];             // Wv transposed fp16 [col][k]

#define HXT_SCALE 16384.0f
#define HXT_INV_SCALE (1.0f/16384.0f)

// ======================= PTX helpers =======================
__device__ __forceinline__ uint32_t smem_to_u32(const void* p) {
    uint32_t a;
    asm("{ .reg .u64 t; cvta.to.shared.u64 t, %1; cvt.u32.u64 %0, t; }" : "=r"(a) : "l"(p));
    return a;
}
#define CP_ASYNC16(dst, src) \
    asm volatile("cp.async.cg.shared.global [%0], [%1], 16;" :: "r"(dst), "l"(src) : "memory")
#define CP_COMMIT() asm volatile("cp.async.commit_group;" ::: "memory")
#define CP_WAIT(n)  asm volatile("cp.async.wait_group %0;" :: "n"(n) : "memory")

__device__ __forceinline__ void ldsm_x4(uint32_t& r0, uint32_t& r1, uint32_t& r2, uint32_t& r3, uint32_t a) {
    asm volatile("ldmatrix.sync.aligned.m8n8.x4.shared.b16 {%0,%1,%2,%3}, [%4];"
                 : "=r"(r0), "=r"(r1), "=r"(r2), "=r"(r3) : "r"(a));
}
__device__ __forceinline__ void ldsm_x2(uint32_t& r0, uint32_t& r1, uint32_t a) {
    asm volatile("ldmatrix.sync.aligned.m8n8.x2.shared.b16 {%0,%1}, [%2];"
                 : "=r"(r0), "=r"(r1) : "r"(a));
}
__device__ __forceinline__ void mma_f16(float c[4], const uint32_t a[4], const uint32_t b[2]) {
    asm volatile("mma.sync.aligned.m16n8k16.row.col.f32.f16.f16.f32 "
                 "{%0,%1,%2,%3}, {%4,%5,%6,%7}, {%8,%9}, {%0,%1,%2,%3};"
                 : "+f"(c[0]), "+f"(c[1]), "+f"(c[2]), "+f"(c[3])
                 : "r"(a[0]), "r"(a[1]), "r"(a[2]), "r"(a[3]), "r"(b[0]), "r"(b[1]));
}

// =================================================================
// wprep: transpose weights to fp16 [col][k] for MMA B operands
// =================================================================
__global__ __launch_bounds__(256) void wprep(
    const float* __restrict__ Wf, const float* __restrict__ Wg,
    const float* __restrict__ Wh, const float* __restrict__ Wv)
{
    const int stride = gridDim.x * 256;
    for (int i = blockIdx.x * 256 + threadIdx.x; i < 3*FF*CC; i += stride) {
        int o = i / (FF*CC);
        int rem = i - o * (FF*CC);
        int c = rem >> 8;
        int k = rem & 255;
        const float* W = (o == 0) ? Wf : (o == 1) ? Wg : Wh;
        g_Wt[i] = __float2half(W[k * FF + c]);
    }
    for (int i = blockIdx.x * 256 + threadIdx.x; i < FF*FF; i += stride) {
        int c = i >> 7, k = i & 127;
        g_Wvt[i] = __float2half(Wv[k * FF + c]);
    }
}

// =================================================================
// proj_mma: fused 3-way projection via fp16 HMMA. (measured-good R13)
// =================================================================
#define PJ_XS    0
#define PJ_XCH   9216
#define PJ_W     36864
#define PJ_WBUF  55296
#define PJ_WO    18432
#define PJ_SMEM  147456

__global__ __launch_bounds__(256, 1) void proj_mma(
    const float* __restrict__ x,
    const float* __restrict__ bf, const float* __restrict__ bg,
    const float* __restrict__ bh)
{
    extern __shared__ char smem[];
    const uint32_t sb = smem_to_u32(smem);
    const int tid  = threadIdx.x;
    const int lane = tid & 31, wid = tid >> 5;
    const int R0 = (wid >> 2) * 32;
    const int C0 = (wid & 3) * 32;
    const int row0 = blockIdx.x * 64;

    #pragma unroll
    for (int c = 0; c < 2; c++) {
        uint32_t bufb = sb + PJ_W + (uint32_t)c * PJ_WBUF;
        #pragma unroll
        for (int o = 0; o < 3; o++) {
            const __half* src0 = g_Wt + o * (FF*CC);
            #pragma unroll
            for (int e = tid; e < 1024; e += 256) {
                int col = e >> 3, seg = e & 7;
                CP_ASYNC16(bufb + (uint32_t)(o*PJ_WO + col*144 + seg*16),
                           src0 + col*CC + c*64 + seg*8);
            }
        }
        CP_COMMIT();
    }

    for (int e = tid; e < 4096; e += 256) {
        int r = e >> 6, seg = e & 63;
        int k = seg * 4;
        float4 v = *(const float4*)&x[(size_t)(row0 + r) * CC + k];
        __half h4[4] = { __float2half(v.x), __float2half(v.y),
                         __float2half(v.z), __float2half(v.w) };
        uint32_t off = PJ_XS + (uint32_t)(k >> 6) * PJ_XCH + r*144 + (k & 63)*2;
        *(uint2*)(smem + off) = *(const uint2*)h4;
    }
    __syncthreads();

    float acc[3][2][4][4];
    #pragma unroll
    for (int o = 0; o < 3; o++)
        #pragma unroll
        for (int mi = 0; mi < 2; mi++)
            #pragma unroll
            for (int ni = 0; ni < 4; ni++)
                #pragma unroll
                for (int q = 0; q < 4; q++) acc[o][mi][ni][q] = 0.f;

    const int arow  = R0 + (lane & 15);
    const int acolB = ((lane >> 4) << 3);
    const int l15   = lane & 15;
    const int brow  = C0 + (l15 & 7);
    const int bcolB = ((l15 >> 3) << 3);

    for (int c = 0; c < 4; c++) {
        if (c < 3) { CP_WAIT(1); } else { CP_WAIT(0); }
        __syncthreads();
        const uint32_t xb = sb + PJ_XS + (uint32_t)c * PJ_XCH;
        const uint32_t wb = sb + PJ_W + (uint32_t)(c & 1) * PJ_WBUF;
        #pragma unroll
        for (int ks = 0; ks < 4; ks++) {
            const int k0 = ks * 16;
            uint32_t aH[2][4];
            #pragma unroll
            for (int mi = 0; mi < 2; mi++) {
                uint32_t ad = xb + (uint32_t)(((arow + mi*16)*72 + k0 + acolB) * 2);
                ldsm_x4(aH[mi][0], aH[mi][1], aH[mi][2], aH[mi][3], ad);
            }
            #pragma unroll
            for (int o = 0; o < 3; o++) {
                uint32_t bH[4][2];
                #pragma unroll
                for (int ni = 0; ni < 4; ni++) {
                    uint32_t bd = wb + (uint32_t)(o*PJ_WO + ((brow + ni*8)*72 + k0 + bcolB) * 2);
                    ldsm_x2(bH[ni][0], bH[ni][1], bd);
                }
                #pragma unroll
                for (int mi = 0; mi < 2; mi++)
                    #pragma unroll
                    for (int ni = 0; ni < 4; ni++)
                        mma_f16(acc[o][mi][ni], aH[mi], bH[ni]);
            }
        }
        __syncthreads();
        if (c + 2 < 4) {
            uint32_t bufb = sb + PJ_W + (uint32_t)(c & 1) * PJ_WBUF;
            #pragma unroll
            for (int o = 0; o < 3; o++) {
                const __half* src0 = g_Wt + o * (FF*CC);
                #pragma unroll
                for (int e = tid; e < 1024; e += 256) {
                    int col = e >> 3, seg = e & 7;
                    CP_ASYNC16(bufb + (uint32_t)(o*PJ_WO + col*144 + seg*16),
                               src0 + col*CC + (c+2)*64 + seg*8);
                }
            }
            CP_COMMIT();
        }
    }

    #pragma unroll
    for (int mi = 0; mi < 2; mi++)
        #pragma unroll
        for (int ni = 0; ni < 4; ni++) {
            int r0q = row0 + R0 + mi*16 + (lane >> 2);
            int col = C0 + ni*8 + 2*(lane & 3);
            float bfc0 = bf[col], bfc1 = bf[col+1];
            float bgc0 = bg[col], bgc1 = bg[col+1];
            float bhc0 = bh[col], bhc1 = bh[col+1];
            #pragma unroll
            for (int h = 0; h < 2; h++) {
                int r = r0q + h*8;
                size_t o = (size_t)r * FF + col;
                __half2 vf = { __float2half(acc[0][mi][ni][h*2+0] + bfc0),
                               __float2half(acc[0][mi][ni][h*2+1] + bfc1) };
                __half2 vg = { __float2half(acc[1][mi][ni][h*2+0] + bgc0),
                               __float2half(acc[1][mi][ni][h*2+1] + bgc1) };
                float2 vh = { acc[2][mi][ni][h*2+0] + bhc0,
                              acc[2][mi][ni][h*2+1] + bhc1 };
                *(__half2*)&g_fx16[o] = vf;
                *(__half2*)&g_gx16[o] = vg;
                *(float2*)&g_hx[o]    = vh;
            }
        }
}

// =================================================================
// score_mma: EXACT R14 measured-good version (2048 CTAs, double-buffer
// prefetch, single fp16 chain, g_spart partials).
// =================================================================
#define S2_A  0
#define S2_B  18432        // 128*72*2
#define S2_CH 36864
#define SC_SMEM (2*S2_CH + 512)

__global__ __launch_bounds__(256, 1) void score_mma()
{
    extern __shared__ char smem[];
    const uint32_t sb = smem_to_u32(smem);
    const int tid  = threadIdx.x;
    const int lane = tid & 31, wid = tid >> 5;
    const int wrow = wid >> 2, wcol = wid & 3;
    const int R0 = wrow * 64, C0 = wcol * 32;
    const int b = blockIdx.z, it = blockIdx.y, jt = blockIdx.x;
    const int row0 = it * 128, col0 = jt * 128;

    const __half* fx = g_fx16 + (size_t)(b*NN + row0) * FF;
    const __half* gx = g_gx16 + (size_t)(b*NN + col0) * FF;

    #pragma unroll
    for (int c = 0; c < 2; c++) {
        uint32_t bufb = sb + c * S2_CH;
        #pragma unroll
        for (int e = tid; e < 1024; e += 256) {
            int r = e >> 3, s = e & 7;
            uint32_t d = bufb + (uint32_t)(r*144 + s*16);
            size_t go = (size_t)r * FF + c*64 + s*8;
            CP_ASYNC16(d + S2_A, fx + go);
            CP_ASYNC16(d + S2_B, gx + go);
        }
        CP_COMMIT();
    }

    float acc[4][4][4];
    #pragma unroll
    for (int mi = 0; mi < 4; mi++)
        #pragma unroll
        for (int ni = 0; ni < 4; ni++)
            #pragma unroll
            for (int q = 0; q < 4; q++) acc[mi][ni][q] = 0.f;

    const int arow  = R0 + (lane & 15);
    const int acolB = ((lane >> 4) << 3);
    const int l15   = lane & 15;
    const int brow  = C0 + (l15 & 7);
    const int bcolB = ((l15 >> 3) << 3);

    #pragma unroll
    for (int c = 0; c < 2; c++) {
        if (c == 0) { CP_WAIT(1); } else { CP_WAIT(0); }
        __syncthreads();
        uint32_t bufb = sb + (uint32_t)c * S2_CH;
        #pragma unroll
        for (int ks = 0; ks < 4; ks++) {
            const int k0 = ks * 16;
            uint32_t aH[4][4], bH[4][2];
            #pragma unroll
            for (int mi = 0; mi < 4; mi++) {
                uint32_t ad = bufb + S2_A + (uint32_t)(((arow + mi*16)*72 + k0 + acolB) * 2);
                ldsm_x4(aH[mi][0], aH[mi][1], aH[mi][2], aH[mi][3], ad);
            }
            #pragma unroll
            for (int ni = 0; ni < 4; ni++) {
                uint32_t bd = bufb + S2_B + (uint32_t)(((brow + ni*8)*72 + k0 + bcolB) * 2);
                ldsm_x2(bH[ni][0], bH[ni][1], bd);
            }
            #pragma unroll
            for (int mi = 0; mi < 4; mi++)
                #pragma unroll
                for (int ni = 0; ni < 4; ni++)
                    mma_f16(acc[mi][ni], aH[mi], bH[ni]);
        }
        __syncthreads();
    }

    float* red = (float*)(smem + 2*S2_CH);
    if (tid < 128) red[tid] = 0.f;
    __syncthreads();

    #pragma unroll
    for (int mi = 0; mi < 4; mi++) {
        float s0 = 0.f, s1 = 0.f;
        #pragma unroll
        for (int ni = 0; ni < 4; ni++) {
            acc[mi][ni][0] = __expf(acc[mi][ni][0]);
            acc[mi][ni][1] = __expf(acc[mi][ni][1]);
            acc[mi][ni][2] = __expf(acc[mi][ni][2]);
            acc[mi][ni][3] = __expf(acc[mi][ni][3]);
            s0 += acc[mi][ni][0] + acc[mi][ni][1];
            s1 += acc[mi][ni][2] + acc[mi][ni][3];
        }
        s0 += __shfl_xor_sync(0xffffffffu, s0, 1);
        s0 += __shfl_xor_sync(0xffffffffu, s0, 2);
        s1 += __shfl_xor_sync(0xffffffffu, s1, 1);
        s1 += __shfl_xor_sync(0xffffffffu, s1, 2);
        if ((lane & 3) == 0) {
            int r = R0 + mi*16 + (lane >> 2);
            atomicAdd(&red[r], s0);
            atomicAdd(&red[r + 8], s1);
        }
    }
    __syncthreads();
    if (tid < 128)
        g_spart[((size_t)(b*NN) + row0 + tid) * 16 + jt] = red[tid];

    __half* stage = (__half*)smem;
    #pragma unroll
    for (int mi = 0; mi < 4; mi++)
        #pragma unroll
        for (int ni = 0; ni < 4; ni++)
            #pragma unroll
            for (int q = 0; q < 4; q++) {
                int i = R0 + mi*16 + (lane >> 2) + ((q >> 1) << 3);
                int j = C0 + ni*8 + 2*(lane & 3) + (q & 1);
                stage[j*136 + i] = __float2half(acc[mi][ni][q]);
            }
    __syncthreads();
    {
        int j = tid >> 1, half = tid & 1;
        uint4* dst = (uint4*)(g_eT + ((size_t)(b*NN + col0 + j))*NN + row0 + half*64);
        const uint4* src = (const uint4*)(stage + j*136 + half*64);
        #pragma unroll
        for (int i = 0; i < 8; i++) dst[i] = src[i];
    }
}

// =================================================================
// hxT_kernel: EXACT R14 measured-good version (reads g_spart).
// =================================================================
__global__ __launch_bounds__(256) void hxT_kernel()
{
    __shared__ __half stage[128][72];
    __shared__ float inv[64];
    const int b = blockIdx.y, n0 = blockIdx.x * 64, t = threadIdx.x;

    if (t < 64) {
        const float* p = &g_spart[((size_t)(b*NN) + n0 + t) * 16];
        float s = 0.f;
        #pragma unroll
        for (int i = 0; i < 16; i++) s += p[i];
        inv[t] = HXT_SCALE / s;
    }
    __syncthreads();

    const float* hx = g_hx + ((size_t)(b*NN + n0)) * FF;

    #pragma unroll
    for (int idx = t; idx < 2048; idx += 256) {
        int r = idx >> 5;
        int seg = idx & 31;
        float4 v = *(const float4*)&hx[(size_t)r * FF + seg*4];
        float s = inv[r];
        stage[seg*4+0][r] = __float2half(v.x * s);
        stage[seg*4+1][r] = __float2half(v.y * s);
        stage[seg*4+2][r] = __float2half(v.z * s);
        stage[seg*4+3][r] = __float2half(v.w * s);
    }
    __syncthreads();

    {
        int f = t & 127, part = t >> 7;
        uint4* dst = (uint4*)(g_hxT + ((size_t)(b*FF) + f) * NN + n0 + part*32);
        const uint4* src = (const uint4*)&stage[f][part*32];
        #pragma unroll
        for (int i = 0; i < 4; i++) dst[i] = src[i];
    }
}

// =================================================================
// out_mma: R14 4x2 layout, NOW 4-stage cp.async pipeline, 2 CTAs/SM.
// grid (mt=32, b=8), 256 threads.
// =================================================================
#define O_A  0
#define O_B  18432
#define O_CH 27648
#define OT_SMEM (4*O_CH)   // 110592

__global__ __launch_bounds__(256, 2) void out_mma()
{
    extern __shared__ char smem[];
    const uint32_t sb = smem_to_u32(smem);
    const int tid  = threadIdx.x;
    const int lane = tid & 31, wid = tid >> 5;
    const int wrow = wid & 3;
    const int wcol = wid >> 2;
    const int R0 = wrow * 32;
    const int C0 = wcol * 32;
    const int b = blockIdx.y, m0 = blockIdx.x * 64;

    const __half* Ah = g_hxT + (size_t)b * FF * NN;
    const __half* Bm = g_eT + (size_t)b * NN * NN + (size_t)m0 * NN;

    auto fill = [&](int buf, int kc) {
        uint32_t bufb = sb + (uint32_t)buf * O_CH;
        #pragma unroll
        for (int e = tid; e < 1024; e += 256) {
            int r = e >> 3, s = e & 7;
            size_t go = (size_t)r * NN + (size_t)kc*64 + s*8;
            CP_ASYNC16(bufb + O_A + (uint32_t)(r*144 + s*16), Ah + go);
        }
        #pragma unroll
        for (int e = tid; e < 512; e += 256) {
            int r = e >> 3, s = e & 7;
            size_t go = (size_t)r * NN + (size_t)kc*64 + s*8;
            CP_ASYNC16(bufb + O_B + (uint32_t)(r*144 + s*16), Bm + go);
        }
        CP_COMMIT();
    };

    float acc[2][4][4];
    #pragma unroll
    for (int mi = 0; mi < 2; mi++)
        #pragma unroll
        for (int ni = 0; ni < 4; ni++)
            #pragma unroll
            for (int q = 0; q < 4; q++) acc[mi][ni][q] = 0.f;

    fill(0, 0);
    fill(1, 1);
    fill(2, 2);
    fill(3, 3);

    const int arow  = R0 + (lane & 15);
    const int acolB = ((lane >> 4) << 3);
    const int bn0   = C0 + ((lane >> 4) << 3) + (lane & 7);
    const int bk    = ((lane >> 3) & 1) << 3;

    for (int kc = 0; kc < 32; kc++) {
        if (kc == 31)      { CP_WAIT(0); }
        else if (kc == 30) { CP_WAIT(1); }
        else if (kc == 29) { CP_WAIT(2); }
        else               { CP_WAIT(3); }
        __syncthreads();
        uint32_t bufb = sb + (uint32_t)(kc & 3) * O_CH;
        #pragma unroll
        for (int ks = 0; ks < 4; ks++) {
            const int k0 = ks * 16;
            uint32_t aH[2][4], bb[2][4];
            #pragma unroll
            for (int mi = 0; mi < 2; mi++) {
                uint32_t ad = bufb + O_A + (uint32_t)(((arow + mi*16)*72 + k0 + acolB) * 2);
                ldsm_x4(aH[mi][0], aH[mi][1], aH[mi][2], aH[mi][3], ad);
            }
            #pragma unroll
            for (int g = 0; g < 2; g++) {
                uint32_t bd = bufb + O_B + (uint32_t)(((bn0 + g*16)*72 + k0 + bk) * 2);
                ldsm_x4(bb[g][0], bb[g][1], bb[g][2], bb[g][3], bd);
            }
            #pragma unroll
            for (int mi = 0; mi < 2; mi++)
                #pragma unroll
                for (int g = 0; g < 2; g++) {
                    mma_f16(acc[mi][g*2+0], aH[mi], &bb[g][0]);
                    mma_f16(acc[mi][g*2+1], aH[mi], &bb[g][2]);
                }
        }
        __syncthreads();
        if (kc + 4 < 32) fill(kc & 3, kc + 4);
    }

    #pragma unroll
    for (int mi = 0; mi < 2; mi++)
        #pragma unroll
        for (int ni = 0; ni < 4; ni++) {
            int f = R0 + mi*16 + (lane >> 2);
            int m = m0 + C0 + ni*8 + 2*(lane & 3);
            float2 v0 = { acc[mi][ni][0]*HXT_INV_SCALE, acc[mi][ni][1]*HXT_INV_SCALE };
            float2 v1 = { acc[mi][ni][2]*HXT_INV_SCALE, acc[mi][ni][3]*HXT_INV_SCALE };
            *(float2*)&g_O[((size_t)(b*FF) + f    ) * NN + m] = v0;
            *(float2*)&g_O[((size_t)(b*FF) + f + 8) * NN + m] = v1;
        }
}

// =================================================================
// final_mma: (R13 measured-good, untouched)
// =================================================================
#define FN_XS   0
#define FN_XCH  9216
#define FN_W    18432
#define FN_WCH  18432
#define FN_SMEM 55296

__global__ __launch_bounds__(256) void final_mma(
    const float* __restrict__ bv, float* __restrict__ out)
{
    extern __shared__ char smem[];
    const uint32_t sb = smem_to_u32(smem);
    const int tid  = threadIdx.x;
    const int lane = tid & 31, wid = tid >> 5;
    const int R0 = (wid >> 2) * 32;
    const int C0 = (wid & 3) * 32;
    const int row0 = blockIdx.x * 64;

    #pragma unroll
    for (int c = 0; c < 2; c++) {
        #pragma unroll
        for (int e = tid; e < 1024; e += 256) {
            int col = e >> 3, seg = e & 7;
            CP_ASYNC16(sb + FN_W + (uint32_t)(c*FN_WCH + col*144 + seg*16),
                       g_Wvt + col*FF + c*64 + seg*8);
        }
    }
    CP_COMMIT();

    const float* A = (const float*)g_O;
    for (int e = tid; e < 2048; e += 256) {
        int r = e >> 5, seg = e & 31;
        int k = seg * 4;
        float4 v = *(const float4*)&A[(size_t)(row0 + r) * FF + k];
        __half h4[4] = { __float2half(v.x), __float2half(v.y),
                         __float2half(v.z), __float2half(v.w) };
        uint32_t off = FN_XS + (uint32_t)(k >> 6) * FN_XCH + r*144 + (k & 63)*2;
        *(uint2*)(smem + off) = *(const uint2*)h4;
    }
    CP_WAIT(0);
    __syncthreads();

    float acc[2][4][4];
    #pragma unroll
    for (int mi = 0; mi < 2; mi++)
        #pragma unroll
        for (int ni = 0; ni < 4; ni++)
            #pragma unroll
            for (int q = 0; q < 4; q++) acc[mi][ni][q] = 0.f;

    const int arow  = R0 + (lane & 15);
    const int acolB = ((lane >> 4) << 3);
    const int l15   = lane & 15;
    const int brow  = C0 + (l15 & 7);
    const int bcolB = ((l15 >> 3) << 3);

    #pragma unroll
    for (int c = 0; c < 2; c++) {
        const uint32_t xb = sb + FN_XS + (uint32_t)c * FN_XCH;
        const uint32_t wb = sb + FN_W  + (uint32_t)c * FN_WCH;
        #pragma unroll
        for (int ks = 0; ks < 4; ks++) {
            const int k0 = ks * 16;
            uint32_t aH[2][4], bH[4][2];
            #pragma unroll
            for (int mi = 0; mi < 2; mi++) {
                uint32_t ad = xb + (uint32_t)(((arow + mi*16)*72 + k0 + acolB) * 2);
                ldsm_x4(aH[mi][0], aH[mi][1], aH[mi][2], aH[mi][3], ad);
            }
            #pragma unroll
            for (int ni = 0; ni < 4; ni++) {
                uint32_t bd = wb + (uint32_t)(((brow + ni*8)*72 + k0 + bcolB) * 2);
                ldsm_x2(bH[ni][0], bH[ni][1], bd);
            }
            #pragma unroll
            for (int mi = 0; mi < 2; mi++)
                #pragma unroll
                for (int ni = 0; ni < 4; ni++)
                    mma_f16(acc[mi][ni], aH[mi], bH[ni]);
        }
    }

    #pragma unroll
    for (int mi = 0; mi < 2; mi++)
        #pragma unroll
        for (int ni = 0; ni < 4; ni++) {
            int r0q = row0 + R0 + mi*16 + (lane >> 2);
            int col = C0 + ni*8 + 2*(lane & 3);
            float b0 = bv[col], b1 = bv[col+1];
            #pragma unroll
            for (int h = 0; h < 2; h++) {
                int r = r0q + h*8;
                float2 v = { acc[mi][ni][h*2+0] + b0, acc[mi][ni][h*2+1] + b1 };
                *(float2*)&out[(size_t)r * FF + col] = v;
            }
        }
}

// =================================================================
extern "C" void kernel_launch(void* const* d_in, const int* in_sizes, int n_in,
                              void* d_out, int out_size)
{
    const float* x  = (const float*)d_in[0];
    const float* Wf = (const float*)d_in[1];
    const float* bf = (const float*)d_in[2];
    const float* Wg = (const float*)d_in[3];
    const float* bg = (const float*)d_in[4];
    const float* Wh = (const float*)d_in[5];
    const float* bh = (const float*)d_in[6];
    const float* Wv = (const float*)d_in[7];
    const float* bv = (const float*)d_in[8];
    float* out = (float*)d_out;

    cudaFuncSetAttribute(proj_mma,  cudaFuncAttributeMaxDynamicSharedMemorySize, PJ_SMEM);
    cudaFuncSetAttribute(score_mma, cudaFuncAttributeMaxDynamicSharedMemorySize, SC_SMEM);
    cudaFuncSetAttribute(out_mma,   cudaFuncAttributeMaxDynamicSharedMemorySize, OT_SMEM);
    cudaFuncSetAttribute(final_mma, cudaFuncAttributeMaxDynamicSharedMemorySize, FN_SMEM);

    // weight transpose + fp16 conversion
    wprep<<<128, 256>>>(Wf, Wg, Wh, Wv);

    // fused projections via HMMA: fx/gx -> fp16, hx -> fp32
    proj_mma<<<MTOT/64, 256, PJ_SMEM>>>(x, bf, bg, bh);

    // scores + exp + transposed fp16 store + partial row sums
    score_mma<<<dim3(16, 16, 8), 256, SC_SMEM>>>();

    // hxT = hx / rowsum * 2^14, transposed, fp16
    hxT_kernel<<<dim3(32, 8), 256>>>();

    // O = hxT @ eT^T * 2^-14
    out_mma<<<dim3(32, 8), 256, OT_SMEM>>>();

    // final: reshape([B,F,N] flat as [B,N,F]) @ Wv + bv via HMMA
    final_mma<<<MTOT/64, 256, FN_SMEM>>>(bv, out);
}

// round 17
// speedup vs baseline: 1.0554x; 1.0349x over previous
#include <cuda_runtime.h>
#include <cuda_bf16.h>
#include <cuda_fp16.h>
#include <cstdint>

#define BB 8
#define NN 2048
#define CC 256
#define FF 128
#define MTOT (BB*NN)   // 16384

// ---------------- scratch (no cudaMalloc allowed) ----------------
__device__ __half        g_fx16[MTOT*FF];          // 4 MB
__device__ __half        g_gx16[MTOT*FF];          // 4 MB
__device__ float         g_hx [MTOT*FF];           // 8 MB
__device__ __half        g_hxT[(size_t)BB*FF*NN];  // [b][f][n] fp16 (scaled)
__device__ __half        g_eT[(size_t)BB*NN*NN];   // [b][m][n] fp16, 64 MB
__device__ float         g_spart[(size_t)BB*NN*16];// partial row sums
__device__ __half        g_O16[MTOT*FF];           // [b][f][m] fp16, 4 MB
__device__ __half        g_Wt[3*FF*CC];            // Wf/Wg/Wh transposed fp16 [o][col][k]
__device__ __half        g_Wvt[FF*FF];             // Wv transposed fp16 [col][k]

#define HXT_SCALE 16384.0f
#define HXT_INV_SCALE (1.0f/16384.0f)

// ======================= PTX helpers =======================
__device__ __forceinline__ uint32_t smem_to_u32(const void* p) {
    uint32_t a;
    asm("{ .reg .u64 t; cvta.to.shared.u64 t, %1; cvt.u32.u64 %0, t; }" : "=r"(a) : "l"(p));
    return a;
}
#define CP_ASYNC16(dst, src) \
    asm volatile("cp.async.cg.shared.global [%0], [%1], 16;" :: "r"(dst), "l"(src) : "memory")
#define CP_COMMIT() asm volatile("cp.async.commit_group;" ::: "memory")
#define CP_WAIT(n)  asm volatile("cp.async.wait_group %0;" :: "n"(n) : "memory")

__device__ __forceinline__ void ldsm_x4(uint32_t& r0, uint32_t& r1, uint32_t& r2, uint32_t& r3, uint32_t a) {
    asm volatile("ldmatrix.sync.aligned.m8n8.x4.shared.b16 {%0,%1,%2,%3}, [%4];"
                 : "=r"(r0), "=r"(r1), "=r"(r2), "=r"(r3) : "r"(a));
}
__device__ __forceinline__ void ldsm_x2(uint32_t& r0, uint32_t& r1, uint32_t a) {
    asm volatile("ldmatrix.sync.aligned.m8n8.x2.shared.b16 {%0,%1}, [%2];"
                 : "=r"(r0), "=r"(r1) : "r"(a));
}
__device__ __forceinline__ void mma_f16(float c[4], const uint32_t a[4], const uint32_t b[2]) {
    asm volatile("mma.sync.aligned.m16n8k16.row.col.f32.f16.f16.f32 "
                 "{%0,%1,%2,%3}, {%4,%5,%6,%7}, {%8,%9}, {%0,%1,%2,%3};"
                 : "+f"(c[0]), "+f"(c[1]), "+f"(c[2]), "+f"(c[3])
                 : "r"(a[0]), "r"(a[1]), "r"(a[2]), "r"(a[3]), "r"(b[0]), "r"(b[1]));
}

// =================================================================
// wprep: transpose weights to fp16 [col][k] for MMA B operands
// =================================================================
__global__ __launch_bounds__(256) void wprep(
    const float* __restrict__ Wf, const float* __restrict__ Wg,
    const float* __restrict__ Wh, const float* __restrict__ Wv)
{
    const int stride = gridDim.x * 256;
    for (int i = blockIdx.x * 256 + threadIdx.x; i < 3*FF*CC; i += stride) {
        int o = i / (FF*CC);
        int rem = i - o * (FF*CC);
        int c = rem >> 8;
        int k = rem & 255;
        const float* W = (o == 0) ? Wf : (o == 1) ? Wg : Wh;
        g_Wt[i] = __float2half(W[k * FF + c]);
    }
    for (int i = blockIdx.x * 256 + threadIdx.x; i < FF*FF; i += stride) {
        int c = i >> 7, k = i & 127;
        g_Wvt[i] = __float2half(Wv[k * FF + c]);
    }
}

// =================================================================
// proj_mma: fused 3-way projection via fp16 HMMA. (measured-good R13)
// =================================================================
#define PJ_XS    0
#define PJ_XCH   9216
#define PJ_W     36864
#define PJ_WBUF  55296
#define PJ_WO    18432
#define PJ_SMEM  147456

__global__ __launch_bounds__(256, 1) void proj_mma(
    const float* __restrict__ x,
    const float* __restrict__ bf, const float* __restrict__ bg,
    const float* __restrict__ bh)
{
    extern __shared__ char smem[];
    const uint32_t sb = smem_to_u32(smem);
    const int tid  = threadIdx.x;
    const int lane = tid & 31, wid = tid >> 5;
    const int R0 = (wid >> 2) * 32;
    const int C0 = (wid & 3) * 32;
    const int row0 = blockIdx.x * 64;

    #pragma unroll
    for (int c = 0; c < 2; c++) {
        uint32_t bufb = sb + PJ_W + (uint32_t)c * PJ_WBUF;
        #pragma unroll
        for (int o = 0; o < 3; o++) {
            const __half* src0 = g_Wt + o * (FF*CC);
            #pragma unroll
            for (int e = tid; e < 1024; e += 256) {
                int col = e >> 3, seg = e & 7;
                CP_ASYNC16(bufb + (uint32_t)(o*PJ_WO + col*144 + seg*16),
                           src0 + col*CC + c*64 + seg*8);
            }
        }
        CP_COMMIT();
    }

    for (int e = tid; e < 4096; e += 256) {
        int r = e >> 6, seg = e & 63;
        int k = seg * 4;
        float4 v = *(const float4*)&x[(size_t)(row0 + r) * CC + k];
        __half h4[4] = { __float2half(v.x), __float2half(v.y),
                         __float2half(v.z), __float2half(v.w) };
        uint32_t off = PJ_XS + (uint32_t)(k >> 6) * PJ_XCH + r*144 + (k & 63)*2;
        *(uint2*)(smem + off) = *(const uint2*)h4;
    }
    __syncthreads();

    float acc[3][2][4][4];
    #pragma unroll
    for (int o = 0; o < 3; o++)
        #pragma unroll
        for (int mi = 0; mi < 2; mi++)
            #pragma unroll
            for (int ni = 0; ni < 4; ni++)
                #pragma unroll
                for (int q = 0; q < 4; q++) acc[o][mi][ni][q] = 0.f;

    const int arow  = R0 + (lane & 15);
    const int acolB = ((lane >> 4) << 3);
    const int l15   = lane & 15;
    const int brow  = C0 + (l15 & 7);
    const int bcolB = ((l15 >> 3) << 3);

    for (int c = 0; c < 4; c++) {
        if (c < 3) { CP_WAIT(1); } else { CP_WAIT(0); }
        __syncthreads();
        const uint32_t xb = sb + PJ_XS + (uint32_t)c * PJ_XCH;
        const uint32_t wb = sb + PJ_W + (uint32_t)(c & 1) * PJ_WBUF;
        #pragma unroll
        for (int ks = 0; ks < 4; ks++) {
            const int k0 = ks * 16;
            uint32_t aH[2][4];
            #pragma unroll
            for (int mi = 0; mi < 2; mi++) {
                uint32_t ad = xb + (uint32_t)(((arow + mi*16)*72 + k0 + acolB) * 2);
                ldsm_x4(aH[mi][0], aH[mi][1], aH[mi][2], aH[mi][3], ad);
            }
            #pragma unroll
            for (int o = 0; o < 3; o++) {
                uint32_t bH[4][2];
                #pragma unroll
                for (int ni = 0; ni < 4; ni++) {
                    uint32_t bd = wb + (uint32_t)(o*PJ_WO + ((brow + ni*8)*72 + k0 + bcolB) * 2);
                    ldsm_x2(bH[ni][0], bH[ni][1], bd);
                }
                #pragma unroll
                for (int mi = 0; mi < 2; mi++)
                    #pragma unroll
                    for (int ni = 0; ni < 4; ni++)
                        mma_f16(acc[o][mi][ni], aH[mi], bH[ni]);
            }
        }
        __syncthreads();
        if (c + 2 < 4) {
            uint32_t bufb = sb + PJ_W + (uint32_t)(c & 1) * PJ_WBUF;
            #pragma unroll
            for (int o = 0; o < 3; o++) {
                const __half* src0 = g_Wt + o * (FF*CC);
                #pragma unroll
                for (int e = tid; e < 1024; e += 256) {
                    int col = e >> 3, seg = e & 7;
                    CP_ASYNC16(bufb + (uint32_t)(o*PJ_WO + col*144 + seg*16),
                               src0 + col*CC + (c+2)*64 + seg*8);
                }
            }
            CP_COMMIT();
        }
    }

    #pragma unroll
    for (int mi = 0; mi < 2; mi++)
        #pragma unroll
        for (int ni = 0; ni < 4; ni++) {
            int r0q = row0 + R0 + mi*16 + (lane >> 2);
            int col = C0 + ni*8 + 2*(lane & 3);
            float bfc0 = bf[col], bfc1 = bf[col+1];
            float bgc0 = bg[col], bgc1 = bg[col+1];
            float bhc0 = bh[col], bhc1 = bh[col+1];
            #pragma unroll
            for (int h = 0; h < 2; h++) {
                int r = r0q + h*8;
                size_t o = (size_t)r * FF + col;
                __half2 vf = { __float2half(acc[0][mi][ni][h*2+0] + bfc0),
                               __float2half(acc[0][mi][ni][h*2+1] + bfc1) };
                __half2 vg = { __float2half(acc[1][mi][ni][h*2+0] + bgc0),
                               __float2half(acc[1][mi][ni][h*2+1] + bgc1) };
                float2 vh = { acc[2][mi][ni][h*2+0] + bhc0,
                              acc[2][mi][ni][h*2+1] + bhc1 };
                *(__half2*)&g_fx16[o] = vf;
                *(__half2*)&g_gx16[o] = vg;
                *(float2*)&g_hx[o]    = vh;
            }
        }
}

// =================================================================
// score_mma: EXACT R14 measured-good version.
// =================================================================
#define S2_A  0
#define S2_B  18432        // 128*72*2
#define S2_CH 36864
#define SC_SMEM (2*S2_CH + 512)

__global__ __launch_bounds__(256, 1) void score_mma()
{
    extern __shared__ char smem[];
    const uint32_t sb = smem_to_u32(smem);
    const int tid  = threadIdx.x;
    const int lane = tid & 31, wid = tid >> 5;
    const int wrow = wid >> 2, wcol = wid & 3;
    const int R0 = wrow * 64, C0 = wcol * 32;
    const int b = blockIdx.z, it = blockIdx.y, jt = blockIdx.x;
    const int row0 = it * 128, col0 = jt * 128;

    const __half* fx = g_fx16 + (size_t)(b*NN + row0) * FF;
    const __half* gx = g_gx16 + (size_t)(b*NN + col0) * FF;

    #pragma unroll
    for (int c = 0; c < 2; c++) {
        uint32_t bufb = sb + c * S2_CH;
        #pragma unroll
        for (int e = tid; e < 1024; e += 256) {
            int r = e >> 3, s = e & 7;
            uint32_t d = bufb + (uint32_t)(r*144 + s*16);
            size_t go = (size_t)r * FF + c*64 + s*8;
            CP_ASYNC16(d + S2_A, fx + go);
            CP_ASYNC16(d + S2_B, gx + go);
        }
        CP_COMMIT();
    }

    float acc[4][4][4];
    #pragma unroll
    for (int mi = 0; mi < 4; mi++)
        #pragma unroll
        for (int ni = 0; ni < 4; ni++)
            #pragma unroll
            for (int q = 0; q < 4; q++) acc[mi][ni][q] = 0.f;

    const int arow  = R0 + (lane & 15);
    const int acolB = ((lane >> 4) << 3);
    const int l15   = lane & 15;
    const int brow  = C0 + (l15 & 7);
    const int bcolB = ((l15 >> 3) << 3);

    #pragma unroll
    for (int c = 0; c < 2; c++) {
        if (c == 0) { CP_WAIT(1); } else { CP_WAIT(0); }
        __syncthreads();
        uint32_t bufb = sb + (uint32_t)c * S2_CH;
        #pragma unroll
        for (int ks = 0; ks < 4; ks++) {
            const int k0 = ks * 16;
            uint32_t aH[4][4], bH[4][2];
            #pragma unroll
            for (int mi = 0; mi < 4; mi++) {
                uint32_t ad = bufb + S2_A + (uint32_t)(((arow + mi*16)*72 + k0 + acolB) * 2);
                ldsm_x4(aH[mi][0], aH[mi][1], aH[mi][2], aH[mi][3], ad);
            }
            #pragma unroll
            for (int ni = 0; ni < 4; ni++) {
                uint32_t bd = bufb + S2_B + (uint32_t)(((brow + ni*8)*72 + k0 + bcolB) * 2);
                ldsm_x2(bH[ni][0], bH[ni][1], bd);
            }
            #pragma unroll
            for (int mi = 0; mi < 4; mi++)
                #pragma unroll
                for (int ni = 0; ni < 4; ni++)
                    mma_f16(acc[mi][ni], aH[mi], bH[ni]);
        }
        __syncthreads();
    }

    float* red = (float*)(smem + 2*S2_CH);
    if (tid < 128) red[tid] = 0.f;
    __syncthreads();

    #pragma unroll
    for (int mi = 0; mi < 4; mi++) {
        float s0 = 0.f, s1 = 0.f;
        #pragma unroll
        for (int ni = 0; ni < 4; ni++) {
            acc[mi][ni][0] = __expf(acc[mi][ni][0]);
            acc[mi][ni][1] = __expf(acc[mi][ni][1]);
            acc[mi][ni][2] = __expf(acc[mi][ni][2]);
            acc[mi][ni][3] = __expf(acc[mi][ni][3]);
            s0 += acc[mi][ni][0] + acc[mi][ni][1];
            s1 += acc[mi][ni][2] + acc[mi][ni][3];
        }
        s0 += __shfl_xor_sync(0xffffffffu, s0, 1);
        s0 += __shfl_xor_sync(0xffffffffu, s0, 2);
        s1 += __shfl_xor_sync(0xffffffffu, s1, 1);
        s1 += __shfl_xor_sync(0xffffffffu, s1, 2);
        if ((lane & 3) == 0) {
            int r = R0 + mi*16 + (lane >> 2);
            atomicAdd(&red[r], s0);
            atomicAdd(&red[r + 8], s1);
        }
    }
    __syncthreads();
    if (tid < 128)
        g_spart[((size_t)(b*NN) + row0 + tid) * 16 + jt] = red[tid];

    __half* stage = (__half*)smem;
    #pragma unroll
    for (int mi = 0; mi < 4; mi++)
        #pragma unroll
        for (int ni = 0; ni < 4; ni++)
            #pragma unroll
            for (int q = 0; q < 4; q++) {
                int i = R0 + mi*16 + (lane >> 2) + ((q >> 1) << 3);
                int j = C0 + ni*8 + 2*(lane & 3) + (q & 1);
                stage[j*136 + i] = __float2half(acc[mi][ni][q]);
            }
    __syncthreads();
    {
        int j = tid >> 1, half = tid & 1;
        uint4* dst = (uint4*)(g_eT + ((size_t)(b*NN + col0 + j))*NN + row0 + half*64);
        const uint4* src = (const uint4*)(stage + j*136 + half*64);
        #pragma unroll
        for (int i = 0; i < 8; i++) dst[i] = src[i];
    }
}

// =================================================================
// hxT_kernel: 512 CTAs (32n x 128f tiles) for more MLP.
// grid (64, 8), 256 threads.
// =================================================================
__global__ __launch_bounds__(256) void hxT_kernel()
{
    __shared__ __half stage[128][40];   // [f][n-local], pad 8
    __shared__ float inv[32];
    const int b = blockIdx.y, n0 = blockIdx.x * 32, t = threadIdx.x;

    if (t < 32) {
        const float* p = &g_spart[((size_t)(b*NN) + n0 + t) * 16];
        float s = 0.f;
        #pragma unroll
        for (int i = 0; i < 16; i++) s += p[i];
        inv[t] = HXT_SCALE / s;
    }
    __syncthreads();

    const float* hx = g_hx + ((size_t)(b*NN + n0)) * FF;

    // 32 rows x 128 f: 4096 floats, 16 per thread (4 float4)
    #pragma unroll
    for (int idx = t; idx < 1024; idx += 256) {
        int r = idx >> 5;            // n-local 0..31
        int seg = idx & 31;          // f-group of 4
        float4 v = *(const float4*)&hx[(size_t)r * FF + seg*4];
        float s = inv[r];
        stage[seg*4+0][r] = __float2half(v.x * s);
        stage[seg*4+1][r] = __float2half(v.y * s);
        stage[seg*4+2][r] = __float2half(v.z * s);
        stage[seg*4+3][r] = __float2half(v.w * s);
    }
    __syncthreads();

    // store: f = t&127, part = t>>7 (2 parts x 16 n)
    {
        int f = t & 127, part = t >> 7;
        uint4* dst = (uint4*)(g_hxT + ((size_t)(b*FF) + f) * NN + n0 + part*16);
        const uint4* src = (const uint4*)&stage[f][part*16];
        #pragma unroll
        for (int i = 0; i < 2; i++) dst[i] = src[i];
    }
}

// =================================================================
// out_mma: EXACT R14 3-stage 4x2-layout version, but epilogue stores
// fp16 to g_O16 (precision-neutral: final converts to fp16 anyway).
// grid (mt=32, b=8), 256 threads, 2 CTAs/SM.
// =================================================================
#define O_A  0
#define O_B  18432
#define O_CH 27648
#define OT_SMEM (3*O_CH)   // 82944

__global__ __launch_bounds__(256, 2) void out_mma()
{
    extern __shared__ char smem[];
    const uint32_t sb = smem_to_u32(smem);
    const int tid  = threadIdx.x;
    const int lane = tid & 31, wid = tid >> 5;
    const int wrow = wid & 3;
    const int wcol = wid >> 2;
    const int R0 = wrow * 32;
    const int C0 = wcol * 32;
    const int b = blockIdx.y, m0 = blockIdx.x * 64;

    const __half* Ah = g_hxT + (size_t)b * FF * NN;
    const __half* Bm = g_eT + (size_t)b * NN * NN + (size_t)m0 * NN;

    auto fill = [&](int buf, int kc) {
        uint32_t bufb = sb + (uint32_t)buf * O_CH;
        #pragma unroll
        for (int e = tid; e < 1024; e += 256) {
            int r = e >> 3, s = e & 7;
            size_t go = (size_t)r * NN + (size_t)kc*64 + s*8;
            CP_ASYNC16(bufb + O_A + (uint32_t)(r*144 + s*16), Ah + go);
        }
        #pragma unroll
        for (int e = tid; e < 512; e += 256) {
            int r = e >> 3, s = e & 7;
            size_t go = (size_t)r * NN + (size_t)kc*64 + s*8;
            CP_ASYNC16(bufb + O_B + (uint32_t)(r*144 + s*16), Bm + go);
        }
        CP_COMMIT();
    };

    float acc[2][4][4];
    #pragma unroll
    for (int mi = 0; mi < 2; mi++)
        #pragma unroll
        for (int ni = 0; ni < 4; ni++)
            #pragma unroll
            for (int q = 0; q < 4; q++) acc[mi][ni][q] = 0.f;

    fill(0, 0);
    fill(1, 1);
    fill(2, 2);

    const int arow  = R0 + (lane & 15);
    const int acolB = ((lane >> 4) << 3);
    const int bn0   = C0 + ((lane >> 4) << 3) + (lane & 7);
    const int bk    = ((lane >> 3) & 1) << 3;

    for (int kc = 0; kc < 32; kc++) {
        if (kc == 31)      { CP_WAIT(0); }
        else if (kc == 30) { CP_WAIT(1); }
        else               { CP_WAIT(2); }
        __syncthreads();
        uint32_t bufb = sb + (uint32_t)(kc % 3) * O_CH;
        #pragma unroll
        for (int ks = 0; ks < 4; ks++) {
            const int k0 = ks * 16;
            uint32_t aH[2][4], bb[2][4];
            #pragma unroll
            for (int mi = 0; mi < 2; mi++) {
                uint32_t ad = bufb + O_A + (uint32_t)(((arow + mi*16)*72 + k0 + acolB) * 2);
                ldsm_x4(aH[mi][0], aH[mi][1], aH[mi][2], aH[mi][3], ad);
            }
            #pragma unroll
            for (int g = 0; g < 2; g++) {
                uint32_t bd = bufb + O_B + (uint32_t)(((bn0 + g*16)*72 + k0 + bk) * 2);
                ldsm_x4(bb[g][0], bb[g][1], bb[g][2], bb[g][3], bd);
            }
            #pragma unroll
            for (int mi = 0; mi < 2; mi++)
                #pragma unroll
                for (int g = 0; g < 2; g++) {
                    mma_f16(acc[mi][g*2+0], aH[mi], &bb[g][0]);
                    mma_f16(acc[mi][g*2+1], aH[mi], &bb[g][2]);
                }
        }
        __syncthreads();
        if (kc + 3 < 32) fill(kc % 3, kc + 3);
    }

    // epilogue: fp16 stores to g_O16, scale 2^-14
    #pragma unroll
    for (int mi = 0; mi < 2; mi++)
        #pragma unroll
        for (int ni = 0; ni < 4; ni++) {
            int f = R0 + mi*16 + (lane >> 2);
            int m = m0 + C0 + ni*8 + 2*(lane & 3);
            __half2 v0 = { __float2half(acc[mi][ni][0]*HXT_INV_SCALE),
                           __float2half(acc[mi][ni][1]*HXT_INV_SCALE) };
            __half2 v1 = { __float2half(acc[mi][ni][2]*HXT_INV_SCALE),
                           __float2half(acc[mi][ni][3]*HXT_INV_SCALE) };
            *(__half2*)&g_O16[((size_t)(b*FF) + f    ) * NN + m] = v0;
            *(__half2*)&g_O16[((size_t)(b*FF) + f + 8) * NN + m] = v1;
        }
}

// =================================================================
// final_mma: out = g_O16(flat [16384][128]) @ Wv + bv, fp16 HMMA.
// A now cp.async'd directly (no fp32 load+convert).
// =================================================================
#define FN_XS   0
#define FN_XCH  9216
#define FN_W    18432
#define FN_WCH  18432
#define FN_SMEM 55296

__global__ __launch_bounds__(256) void final_mma(
    const float* __restrict__ bv, float* __restrict__ out)
{
    extern __shared__ char smem[];
    const uint32_t sb = smem_to_u32(smem);
    const int tid  = threadIdx.x;
    const int lane = tid & 31, wid = tid >> 5;
    const int R0 = (wid >> 2) * 32;
    const int C0 = (wid & 3) * 32;
    const int row0 = blockIdx.x * 64;

    // cp.async A (g_O16 rows) + Wv, both chunks
    #pragma unroll
    for (int c = 0; c < 2; c++) {
        #pragma unroll
        for (int e = tid; e < 512; e += 256) {
            int r = e >> 3, seg = e & 7;
            CP_ASYNC16(sb + FN_XS + (uint32_t)(c*FN_XCH + r*144 + seg*16),
                       g_O16 + (size_t)(row0 + r) * FF + c*64 + seg*8);
        }
        #pragma unroll
        for (int e = tid; e < 1024; e += 256) {
            int col = e >> 3, seg = e & 7;
            CP_ASYNC16(sb + FN_W + (uint32_t)(c*FN_WCH + col*144 + seg*16),
                       g_Wvt + col*FF + c*64 + seg*8);
        }
    }
    CP_COMMIT();
    CP_WAIT(0);
    __syncthreads();

    float acc[2][4][4];
    #pragma unroll
    for (int mi = 0; mi < 2; mi++)
        #pragma unroll
        for (int ni = 0; ni < 4; ni++)
            #pragma unroll
            for (int q = 0; q < 4; q++) acc[mi][ni][q] = 0.f;

    const int arow  = R0 + (lane & 15);
    const int acolB = ((lane >> 4) << 3);
    const int l15   = lane & 15;
    const int brow  = C0 + (l15 & 7);
    const int bcolB = ((l15 >> 3) << 3);

    #pragma unroll
    for (int c = 0; c < 2; c++) {
        const uint32_t xb = sb + FN_XS + (uint32_t)c * FN_XCH;
        const uint32_t wb = sb + FN_W  + (uint32_t)c * FN_WCH;
        #pragma unroll
        for (int ks = 0; ks < 4; ks++) {
            const int k0 = ks * 16;
            uint32_t aH[2][4], bH[4][2];
            #pragma unroll
            for (int mi = 0; mi < 2; mi++) {
                uint32_t ad = xb + (uint32_t)(((arow + mi*16)*72 + k0 + acolB) * 2);
                ldsm_x4(aH[mi][0], aH[mi][1], aH[mi][2], aH[mi][3], ad);
            }
            #pragma unroll
            for (int ni = 0; ni < 4; ni++) {
                uint32_t bd = wb + (uint32_t)(((brow + ni*8)*72 + k0 + bcolB) * 2);
                ldsm_x2(bH[ni][0], bH[ni][1], bd);
            }
            #pragma unroll
            for (int mi = 0; mi < 2; mi++)
                #pragma unroll
                for (int ni = 0; ni < 4; ni++)
                    mma_f16(acc[mi][ni], aH[mi], bH[ni]);
        }
    }

    #pragma unroll
    for (int mi = 0; mi < 2; mi++)
        #pragma unroll
        for (int ni = 0; ni < 4; ni++) {
            int r0q = row0 + R0 + mi*16 + (lane >> 2);
            int col = C0 + ni*8 + 2*(lane & 3);
            float b0 = bv[col], b1 = bv[col+1];
            #pragma unroll
            for (int h = 0; h < 2; h++) {
                int r = r0q + h*8;
                float2 v = { acc[mi][ni][h*2+0] + b0, acc[mi][ni][h*2+1] + b1 };
                *(float2*)&out[(size_t)r * FF + col] = v;
            }
        }
}

// =================================================================
extern "C" void kernel_launch(void* const* d_in, const int* in_sizes, int n_in,
                              void* d_out, int out_size)
{
    const float* x  = (const float*)d_in[0];
    const float* Wf = (const float*)d_in[1];
    const float* bf = (const float*)d_in[2];
    const float* Wg = (const float*)d_in[3];
    const float* bg = (const float*)d_in[4];
    const float* Wh = (const float*)d_in[5];
    const float* bh = (const float*)d_in[6];
    const float* Wv = (const float*)d_in[7];
    const float* bv = (const float*)d_in[8];
    float* out = (float*)d_out;

    cudaFuncSetAttribute(proj_mma,  cudaFuncAttributeMaxDynamicSharedMemorySize, PJ_SMEM);
    cudaFuncSetAttribute(score_mma, cudaFuncAttributeMaxDynamicSharedMemorySize, SC_SMEM);
    cudaFuncSetAttribute(out_mma,   cudaFuncAttributeMaxDynamicSharedMemorySize, OT_SMEM);
    cudaFuncSetAttribute(final_mma, cudaFuncAttributeMaxDynamicSharedMemorySize, FN_SMEM);

    // weight transpose + fp16 conversion
    wprep<<<128, 256>>>(Wf, Wg, Wh, Wv);

    // fused projections via HMMA: fx/gx -> fp16, hx -> fp32
    proj_mma<<<MTOT/64, 256, PJ_SMEM>>>(x, bf, bg, bh);

    // scores + exp + transposed fp16 store + partial row sums
    score_mma<<<dim3(16, 16, 8), 256, SC_SMEM>>>();

    // hxT = hx / rowsum * 2^14, transposed, fp16
    hxT_kernel<<<dim3(64, 8), 256>>>();

    // O = hxT @ eT^T * 2^-14 -> fp16
    out_mma<<<dim3(32, 8), 256, OT_SMEM>>>();

    // final: reshape([B,F,N] flat as [B,N,F]) @ Wv + bv via HMMA
    final_mma<<<MTOT/64, 256, FN_SMEM>>>(bv, out);
}